// round 5
// baseline (speedup 1.0000x reference)
#include <cuda_runtime.h>
#include <cuda_bf16.h>
#include <cstdint>

#define DI    2048
#define LSEQ  512
#define BT    1024          // B*L
#define GRIDN 148
#define UC    8             // units per block with SMEM-cached weights

// ------------------------- device scratch -------------------------
__device__ float g_xz[(size_t)BT * 4096];      // [bt][x_in(2048) | z(2048)]
__device__ float g_xconv[(size_t)BT * DI];
__device__ float g_gi[(size_t)BT * 6144];
__device__ float g_basedt[(size_t)BT * DI];
__device__ float g_ygated[(size_t)BT * DI];
__device__ float g_xdbl[(size_t)BT * 96];
__device__ float g_bdual[BT * 16];
__device__ float g_scaling[BT];
__device__ float g_spart[(size_t)BT * GRIDN];
__device__ float g_h[2][2 * DI];
__device__ unsigned g_barcnt;

__device__ __forceinline__ float sigmf_(float x) { return 1.f / (1.f + expf(-x)); }
__device__ __forceinline__ float softplusf_(float x) {
    return fmaxf(x, 0.f) + log1pf(expf(-fabsf(x)));
}

// ------------------------- init -------------------------
__global__ void k_init() {
    int i = blockIdx.x * 256 + threadIdx.x;
    if (i < 2 * DI) g_h[1][i] = 0.f;      // h(-1) read buffer
    if (i == 0) g_barcnt = 0u;
}

// ------------------------- generic GEMM: C = act(A @ W^T [+bias]) ----------
// A:[M=1024, lda] row-major, W:[N, ldw] row-major, C:[1024, ldc]
// ACT: 0 none, 1 +bias, 2 softplus(acc + 2*bias)
template <int ACT>
__global__ void __launch_bounds__(256) k_gemm(
    const float* __restrict__ A, int lda,
    const float* __restrict__ W, int ldw,
    const float* __restrict__ bias,
    float* __restrict__ C, int ldc, int N, int K)
{
    __shared__ float As[16][68];
    __shared__ float Bs[16][68];
    int tid = threadIdx.x;
    int bm = blockIdx.y * 64, bn = blockIdx.x * 64;
    int tx = tid & 15, ty = tid >> 4;
    int lr = tid >> 2, lk = (tid & 3) * 4;
    float acc[4][4] = {};
    for (int k0 = 0; k0 < K; k0 += 16) {
        float4 av = *(const float4*)(A + (size_t)(bm + lr) * lda + k0 + lk);
        float4 wv = make_float4(0.f, 0.f, 0.f, 0.f);
        if (bn + lr < N) wv = *(const float4*)(W + (size_t)(bn + lr) * ldw + k0 + lk);
        __syncthreads();
        As[lk][lr] = av.x; As[lk+1][lr] = av.y; As[lk+2][lr] = av.z; As[lk+3][lr] = av.w;
        Bs[lk][lr] = wv.x; Bs[lk+1][lr] = wv.y; Bs[lk+2][lr] = wv.z; Bs[lk+3][lr] = wv.w;
        __syncthreads();
        #pragma unroll
        for (int kk = 0; kk < 16; kk++) {
            float4 a = *(const float4*)&As[kk][ty * 4];
            float4 b = *(const float4*)&Bs[kk][tx * 4];
            float ar[4] = {a.x, a.y, a.z, a.w};
            float br[4] = {b.x, b.y, b.z, b.w};
            #pragma unroll
            for (int i = 0; i < 4; i++)
                #pragma unroll
                for (int j = 0; j < 4; j++)
                    acc[i][j] = fmaf(ar[i], br[j], acc[i][j]);
        }
    }
    #pragma unroll
    for (int i = 0; i < 4; i++) {
        int row = bm + ty * 4 + i;
        #pragma unroll
        for (int j = 0; j < 4; j++) {
            int col = bn + tx * 4 + j;
            if (col < N) {
                float v = acc[i][j];
                if (ACT == 1) v += bias[col];
                if (ACT == 2) { v += 2.f * bias[col]; v = softplusf_(v); }
                C[(size_t)row * ldc + col] = v;
            }
        }
    }
}

// ------------------------- causal conv + silu -------------------------
__global__ void __launch_bounds__(256) k_conv(
    const float* __restrict__ cw, const float* __restrict__ cb)
{
    int idx = blockIdx.x * 256 + threadIdx.x;     // over BT*DI
    int d = idx & (DI - 1);
    int bt = idx >> 11;
    int t = bt & (LSEQ - 1);
    float acc = cb[d];
    #pragma unroll
    for (int k = 0; k < 4; k++) {
        int tt = t + k - 3;
        if (tt >= 0)
            acc = fmaf(g_xz[(size_t)(bt + k - 3) * 4096 + d], cw[d * 4 + k], acc);
    }
    g_xconv[(size_t)bt * DI + d] = acc * sigmf_(acc);   // silu
}

// ------------------------- persistent GRU -------------------------
__global__ void __launch_bounds__(256, 1) k_gru(
    const float* __restrict__ whh, const float* __restrict__ bhh,
    const float* __restrict__ wtw)
{
    extern __shared__ float sm[];
    float* sw = sm;                    // UC*3*DI cached weight rows
    float* sh = sm + UC * 3 * DI;      // 2*DI   h for both batches
    float* sp = sh + 2 * DI;           // 16     per-warp scaling partials

    int bid = blockIdx.x, tid = threadIdx.x;
    int lane = tid & 31, wid = tid >> 5;
    int ustart = bid * 13 + min(bid, 124);
    int ucnt = 13 + (bid < 124 ? 1 : 0);

    // preload SMEM-cached weight rows (units 0..UC-1 of this block)
    for (int u = 0; u < UC; u++)
        for (int g = 0; g < 3; g++) {
            const float4* src = (const float4*)(whh + ((size_t)g * DI + ustart + u) * DI);
            float4* dst = (float4*)(sw + (u * 3 + g) * DI);
            for (int i = tid; i < DI / 4; i += 256) dst[i] = src[i];
        }

    unsigned target = 0;
    for (int t = 0; t < LSEQ; t++) {
        int rb = (t + 1) & 1, wb = t & 1;
        __syncthreads();
        {   // stage h(t-1) for both batches into SMEM (L2-coherent loads)
            const float4* src = (const float4*)g_h[rb];
            float4* dst = (float4*)sh;
            for (int i = tid; i < (2 * DI) / 4; i += 256) dst[i] = __ldcg(src + i);
        }
        __syncthreads();

        float pr0 = 0.f, pr1 = 0.f;
        for (int u = wid; u < ucnt; u += 8) {
            int d = ustart + u;
            float a00 = 0, a01 = 0, a10 = 0, a11 = 0, a20 = 0, a21 = 0;
            const float4* h0p = (const float4*)sh;
            const float4* h1p = (const float4*)(sh + DI);
            if (u < UC) {
                const float4* wr = (const float4*)(sw + (u * 3 + 0) * DI);
                const float4* wz = (const float4*)(sw + (u * 3 + 1) * DI);
                const float4* wn = (const float4*)(sw + (u * 3 + 2) * DI);
                #pragma unroll 4
                for (int i = 0; i < 16; i++) {
                    int k = lane + 32 * i;
                    float4 h0 = h0p[k], h1 = h1p[k];
                    float4 r4 = wr[k], z4 = wz[k], n4 = wn[k];
                    a00 += r4.x*h0.x + r4.y*h0.y + r4.z*h0.z + r4.w*h0.w;
                    a01 += r4.x*h1.x + r4.y*h1.y + r4.z*h1.z + r4.w*h1.w;
                    a10 += z4.x*h0.x + z4.y*h0.y + z4.z*h0.z + z4.w*h0.w;
                    a11 += z4.x*h1.x + z4.y*h1.y + z4.z*h1.z + z4.w*h1.w;
                    a20 += n4.x*h0.x + n4.y*h0.y + n4.z*h0.z + n4.w*h0.w;
                    a21 += n4.x*h1.x + n4.y*h1.y + n4.z*h1.z + n4.w*h1.w;
                }
            } else {
                const float4* wr = (const float4*)(whh + ((size_t)0 * DI + d) * DI);
                const float4* wz = (const float4*)(whh + ((size_t)1 * DI + d) * DI);
                const float4* wn = (const float4*)(whh + ((size_t)2 * DI + d) * DI);
                #pragma unroll 4
                for (int i = 0; i < 16; i++) {
                    int k = lane + 32 * i;
                    float4 h0 = h0p[k], h1 = h1p[k];
                    float4 r4 = __ldg(wr + k), z4 = __ldg(wz + k), n4 = __ldg(wn + k);
                    a00 += r4.x*h0.x + r4.y*h0.y + r4.z*h0.z + r4.w*h0.w;
                    a01 += r4.x*h1.x + r4.y*h1.y + r4.z*h1.z + r4.w*h1.w;
                    a10 += z4.x*h0.x + z4.y*h0.y + z4.z*h0.z + z4.w*h0.w;
                    a11 += z4.x*h1.x + z4.y*h1.y + z4.z*h1.z + z4.w*h1.w;
                    a20 += n4.x*h0.x + n4.y*h0.y + n4.z*h0.z + n4.w*h0.w;
                    a21 += n4.x*h1.x + n4.y*h1.y + n4.z*h1.z + n4.w*h1.w;
                }
            }
            #pragma unroll
            for (int o = 16; o; o >>= 1) {
                a00 += __shfl_xor_sync(0xffffffffu, a00, o);
                a01 += __shfl_xor_sync(0xffffffffu, a01, o);
                a10 += __shfl_xor_sync(0xffffffffu, a10, o);
                a11 += __shfl_xor_sync(0xffffffffu, a11, o);
                a20 += __shfl_xor_sync(0xffffffffu, a20, o);
                a21 += __shfl_xor_sync(0xffffffffu, a21, o);
            }
            if (lane == 0) {
                #pragma unroll
                for (int b = 0; b < 2; b++) {
                    float gr = b ? a01 : a00, gz = b ? a11 : a10, gn = b ? a21 : a20;
                    size_t gib = ((size_t)(b * LSEQ + t)) * 6144 + d;
                    float r  = sigmf_(g_gi[gib]        + gr + bhh[d]);
                    float uz = sigmf_(g_gi[gib + 2048] + gz + bhh[2048 + d]);
                    float nn = tanhf (g_gi[gib + 4096] + r * (gn + bhh[4096 + d]));
                    float hn = (1.f - uz) * nn + uz * sh[b * DI + d];
                    __stcg(&g_h[wb][b * DI + d], hn);
                    float c = hn * wtw[d];
                    if (b) pr1 += c; else pr0 += c;
                }
            }
        }
        if (lane == 0) { sp[wid * 2] = pr0; sp[wid * 2 + 1] = pr1; }
        __threadfence();          // make h writes device-visible before arrival
        __syncthreads();
        if (tid == 0) {
            float s0 = 0.f, s1 = 0.f;
            #pragma unroll
            for (int w2 = 0; w2 < 8; w2++) { s0 += sp[w2 * 2]; s1 += sp[w2 * 2 + 1]; }
            g_spart[(size_t)t * GRIDN + bid]          = s0;   // bt = t        (b=0)
            g_spart[(size_t)(LSEQ + t) * GRIDN + bid] = s1;   // bt = 512 + t  (b=1)
            __threadfence();
            atomicAdd(&g_barcnt, 1u);
        }
        target += GRIDN;
        if (tid == 0) {
            while (*((volatile unsigned*)&g_barcnt) < target) {}
            __threadfence();
        }
        __syncthreads();
    }
}

// ------------------------- scaling reduce (deterministic) -------------------
__global__ void k_scale(const float* __restrict__ wtb, float* __restrict__ dout,
                        int has_tail)
{
    int bt = blockIdx.x * blockDim.x + threadIdx.x;
    if (bt >= BT) return;
    float s = 0.f;
    for (int i = 0; i < GRIDN; i++) s += g_spart[(size_t)bt * GRIDN + i];
    float raw = fminf(fmaxf(s + wtb[0], -10.f), 10.f);
    float sc  = fminf(fmaxf(softplusf_(raw), 0.1f), 10.f);
    g_scaling[bt] = sc;
    if (has_tail && (bt & (LSEQ - 1)) == (LSEQ - 1))
        dout[1048576 + (bt >> 9)] = sc;     // scaling[:, -1, :]
}

// ------------------------- B_dual -------------------------
__global__ void __launch_bounds__(256) k_bdual(
    const float* __restrict__ wc, const float* __restrict__ wtau,
    const float* __restrict__ b0, const float* __restrict__ delta)
{
    int bt = blockIdx.x;
    int lane = threadIdx.x & 31, wid = threadIdx.x >> 5;
    const float4* xc = (const float4*)(g_xconv + (size_t)bt * DI);
    for (int j = wid; j < 10; j += 8) {
        const float4* w = (const float4*)(wc + (size_t)j * DI);
        float a = 0.f;
        for (int i = lane; i < DI / 4; i += 32) {
            float4 xv = xc[i], wv = w[i];
            a += xv.x*wv.x + xv.y*wv.y + xv.z*wv.z + xv.w*wv.w;
        }
        #pragma unroll
        for (int o = 16; o; o >>= 1) a += __shfl_xor_sync(0xffffffffu, a, o);
        if (lane == 0) g_bdual[bt * 16 + j] = sigmf_(a) * b0[j];
    }
    if (wid < 6 && lane == 0) {
        float stg = delta[bt] * g_scaling[bt];
        g_bdual[bt * 16 + 10 + wid] = sigmf_(stg * wtau[wid]) * b0[10 + wid];
    }
}

// ------------------------- SSM scan + y gating -------------------------
__global__ void __launch_bounds__(256) k_scan(
    const float* __restrict__ delta, const float* __restrict__ alog,
    const float* __restrict__ dparam)
{
    int g = blockIdx.x * 256 + threadIdx.x;    // 65536 = 2*2048*16
    int n = g & 15;
    int d = (g >> 4) & (DI - 1);
    int b = g >> 15;
    float Acoef = -expf(alog[d * 16 + n]);
    float Dp = dparam[d];
    float h = 0.f, prev = 0.f;
    for (int t = 0; t < LSEQ; t++) {
        int bt = b * LSEQ + t;
        float stg = delta[bt] * g_scaling[bt];
        float itv = stg - prev; prev = stg;
        float bdt = g_basedt[(size_t)bt * DI + d];
        float dts = fminf(fmaxf(itv * bdt, 1e-6f), 10.f);
        float dA = __expf(fmaxf(dts * Acoef, -20.f));
        float xc = g_xconv[(size_t)bt * DI + d];
        float bd = g_bdual[bt * 16 + n];
        h = fmaf(dA, h, dts * bd * xc);
        float yv = h * g_xdbl[(size_t)bt * 96 + 80 + n];
        yv += __shfl_xor_sync(0xffffffffu, yv, 1);
        yv += __shfl_xor_sync(0xffffffffu, yv, 2);
        yv += __shfl_xor_sync(0xffffffffu, yv, 4);
        yv += __shfl_xor_sync(0xffffffffu, yv, 8);
        if (n == 0) {
            float z = g_xz[(size_t)bt * 4096 + 2048 + d];
            g_ygated[(size_t)bt * DI + d] = (yv + xc * Dp) * (z * sigmf_(z));
        }
    }
}

// ------------------------- launch -------------------------
extern "C" void kernel_launch(void* const* d_in, const int* in_sizes, int n_in,
                              void* d_out, int out_size)
{
    const float* x         = (const float*)d_in[0];
    const float* delta     = (const float*)d_in[1];
    const float* in_proj_w = (const float*)d_in[2];
    const float* conv_w    = (const float*)d_in[3];
    const float* conv_b    = (const float*)d_in[4];
    const float* gru_wih   = (const float*)d_in[5];
    const float* gru_whh   = (const float*)d_in[6];
    const float* gru_bih   = (const float*)d_in[7];
    const float* gru_bhh   = (const float*)d_in[8];
    const float* WT_w      = (const float*)d_in[9];
    const float* WT_b      = (const float*)d_in[10];
    const float* Wc_w      = (const float*)d_in[11];
    const float* Wtau_w    = (const float*)d_in[12];
    const float* B0        = (const float*)d_in[13];
    const float* xproj_w   = (const float*)d_in[14];
    const float* dtproj_w  = (const float*)d_in[15];
    const float* dtproj_b  = (const float*)d_in[16];
    const float* A_log     = (const float*)d_in[17];
    const float* D_param   = (const float*)d_in[18];
    const float* outproj_w = (const float*)d_in[19];
    float* out = (float*)d_out;

    float *p_xz, *p_xconv, *p_gi, *p_xdbl, *p_basedt, *p_ygated;
    cudaGetSymbolAddress((void**)&p_xz, g_xz);
    cudaGetSymbolAddress((void**)&p_xconv, g_xconv);
    cudaGetSymbolAddress((void**)&p_gi, g_gi);
    cudaGetSymbolAddress((void**)&p_xdbl, g_xdbl);
    cudaGetSymbolAddress((void**)&p_basedt, g_basedt);
    cudaGetSymbolAddress((void**)&p_ygated, g_ygated);

    const int smem_gru = (UC * 3 * DI + 2 * DI + 16) * 4;   // 213056 B
    cudaFuncSetAttribute(k_gru, cudaFuncAttributeMaxDynamicSharedMemorySize, smem_gru);

    k_init<<<16, 256>>>();
    // xz = x @ in_proj_w^T   (M=1024, N=4096, K=1024)
    k_gemm<0><<<dim3(64, 16), 256>>>(x, 1024, in_proj_w, 1024, nullptr, p_xz, 4096, 4096, 1024);
    // conv + silu
    k_conv<<<(BT * DI) / 256, 256>>>(conv_w, conv_b);
    // gi = x_conv @ gru_wih^T + bih   (N=6144, K=2048)
    k_gemm<1><<<dim3(96, 16), 256>>>(p_xconv, DI, gru_wih, DI, gru_bih, p_gi, 6144, 6144, DI);
    // x_dbl = x_conv @ xproj_w^T   (N=96, K=2048)
    k_gemm<0><<<dim3(2, 16), 256>>>(p_xconv, DI, xproj_w, DI, nullptr, p_xdbl, 96, 96, DI);
    // persistent GRU (writes h trajectory partials -> g_spart)
    k_gru<<<GRIDN, 256, smem_gru>>>(gru_whh, gru_bhh, WT_w);
    // scaling + tail output
    k_scale<<<4, 256>>>(WT_b, out, out_size >= 1048578 ? 1 : 0);
    // base_dt = softplus(dt_low @ dtproj_w^T + 2*dtproj_b)  (N=2048, K=64, lda=96)
    k_gemm<2><<<dim3(32, 16), 256>>>(p_xdbl, 96, dtproj_w, 64, dtproj_b, p_basedt, DI, DI, 64);
    // B_dual
    k_bdual<<<BT, 256>>>(Wc_w, Wtau_w, B0, delta);
    // SSM scan + gating
    k_scan<<<256, 256>>>(delta, A_log, D_param);
    // out = y_gated @ outproj_w^T   (N=1024, K=2048)
    k_gemm<0><<<dim3(16, 16), 256>>>(p_ygated, DI, outproj_w, DI, nullptr, out, 1024, 1024, DI);
}